// round 1
// baseline (speedup 1.0000x reference)
#include <cuda_runtime.h>
#include <cstdint>

// Problem constants (from reference): B=8, N=C=2048, heads=8 -> scale = 1/16.
#define NB 8
#define NN 2048
#define NN2 (2048*2048)
#define SCALE 0.0625f

// Scratch (no cudaMalloc allowed): q intermediate (128 MB), col means, row maxes.
__device__ float        g_q[(size_t)NB * NN2];
__device__ float        g_v[NB * NN];   // column means of x: v[b][c] = mean_n x[b][n][c]
__device__ unsigned int g_m[NB * NN];   // ordered-uint encoded row maxes of attn

// ---- monotone float<->uint order mapping (for atomicMax over signed floats) ----
__device__ __forceinline__ unsigned int float_ord(float f) {
    unsigned int u = __float_as_uint(f);
    return (u & 0x80000000u) ? ~u : (u | 0x80000000u);
}
__device__ __forceinline__ float ord_float(unsigned int o) {
    unsigned int u = (o & 0x80000000u) ? (o ^ 0x80000000u) : ~o;
    return __uint_as_float(u);
}

// ---- init: zero means, -inf (ord 0) maxes -----------------------------------
__global__ void init_kernel() {
    int i = blockIdx.x * 256 + threadIdx.x;
    if (i < NB * NN) { g_v[i] = 0.0f; g_m[i] = 0u; }
}

// ---- column means: v[b][c] = (1/N) sum_n x[b][n][c] -------------------------
// grid (B, 8 c-chunks, 8 n-slices), 256 threads
__global__ void mean_kernel(const float* __restrict__ x) {
    int b = blockIdx.x;
    int c = blockIdx.y * 256 + threadIdx.x;
    int n0 = blockIdx.z * 256;
    const float* xp = x + ((size_t)b * NN + n0) * NN + c;
    float s = 0.0f;
    #pragma unroll 8
    for (int n = 0; n < 256; n++) s += xp[(size_t)n * NN];
    atomicAdd(&g_v[b * NN + c], s * (1.0f / (float)NN));
}

// ---- SGEMM common tiling ----------------------------------------------------
#define BM 128
#define BN 128
#define BK 8

// q[b] = Wq (MxK, row-major) * x[b] (KxN, row-major)    [NN gemm]
__global__ __launch_bounds__(256, 2) void qgemm_kernel(const float* __restrict__ Wq,
                                                       const float* __restrict__ x) {
    __shared__ float As[BK][BM];
    __shared__ float Bs[BK][BN];
    const int b = blockIdx.z;
    const float* A  = Wq;
    const float* Bm = x   + (size_t)b * NN2;
    float*       C  = g_q + (size_t)b * NN2;
    const int row0 = blockIdx.y * BM;
    const int col0 = blockIdx.x * BN;
    const int t  = threadIdx.x;
    const int aRow = t >> 1, aK = (t & 1) * 4;      // A: 128 rows x 8 k (transpose to smem)
    const int bRow = t >> 5, bCol = (t & 31) * 4;   // B: 8 rows x 128 cols (direct)
    const int tx = t & 15, ty = t >> 4;

    float acc[8][8];
    #pragma unroll
    for (int i = 0; i < 8; i++)
        #pragma unroll
        for (int j = 0; j < 8; j++) acc[i][j] = 0.0f;

    for (int kt = 0; kt < NN; kt += BK) {
        float4 av = *(const float4*)(A + (size_t)(row0 + aRow) * NN + kt + aK);
        As[aK + 0][aRow] = av.x; As[aK + 1][aRow] = av.y;
        As[aK + 2][aRow] = av.z; As[aK + 3][aRow] = av.w;
        *(float4*)&Bs[bRow][bCol] =
            *(const float4*)(Bm + (size_t)(kt + bRow) * NN + col0 + bCol);
        __syncthreads();
        #pragma unroll
        for (int k = 0; k < BK; k++) {
            float a[8], bb[8];
            *(float4*)(a)      = *(float4*)&As[k][ty * 8];
            *(float4*)(a + 4)  = *(float4*)&As[k][ty * 8 + 4];
            *(float4*)(bb)     = *(float4*)&Bs[k][tx * 8];
            *(float4*)(bb + 4) = *(float4*)&Bs[k][tx * 8 + 4];
            #pragma unroll
            for (int i = 0; i < 8; i++)
                #pragma unroll
                for (int j = 0; j < 8; j++) acc[i][j] += a[i] * bb[j];
        }
        __syncthreads();
    }
    #pragma unroll
    for (int i = 0; i < 8; i++) {
        float* cp = C + (size_t)(row0 + ty * 8 + i) * NN + col0 + tx * 8;
        *(float4*)(cp)     = *(float4*)&acc[i][0];
        *(float4*)(cp + 4) = *(float4*)&acc[i][4];
    }
}

// rowmax[b][n] = max_m sum_c q[b][n][c] * x[b][m][c]   [NT gemm, max epilogue]
__global__ __launch_bounds__(256, 2) void attn_max_kernel(const float* __restrict__ x) {
    __shared__ float Qs[BK][BM];
    __shared__ float Xs[BK][BN];
    const int b = blockIdx.z;
    const float* Q = g_q + (size_t)b * NN2;
    const float* X = x   + (size_t)b * NN2;
    const int row0 = blockIdx.y * BM;   // n
    const int col0 = blockIdx.x * BN;   // m
    const int t  = threadIdx.x;
    const int lRow = t >> 1, lK = (t & 1) * 4;   // both operands K-contiguous
    const int tx = t & 15, ty = t >> 4;

    float acc[8][8];
    #pragma unroll
    for (int i = 0; i < 8; i++)
        #pragma unroll
        for (int j = 0; j < 8; j++) acc[i][j] = 0.0f;

    for (int kt = 0; kt < NN; kt += BK) {
        float4 qv = *(const float4*)(Q + (size_t)(row0 + lRow) * NN + kt + lK);
        Qs[lK + 0][lRow] = qv.x; Qs[lK + 1][lRow] = qv.y;
        Qs[lK + 2][lRow] = qv.z; Qs[lK + 3][lRow] = qv.w;
        float4 xv = *(const float4*)(X + (size_t)(col0 + lRow) * NN + kt + lK);
        Xs[lK + 0][lRow] = xv.x; Xs[lK + 1][lRow] = xv.y;
        Xs[lK + 2][lRow] = xv.z; Xs[lK + 3][lRow] = xv.w;
        __syncthreads();
        #pragma unroll
        for (int k = 0; k < BK; k++) {
            float a[8], bb[8];
            *(float4*)(a)      = *(float4*)&Qs[k][ty * 8];
            *(float4*)(a + 4)  = *(float4*)&Qs[k][ty * 8 + 4];
            *(float4*)(bb)     = *(float4*)&Xs[k][tx * 8];
            *(float4*)(bb + 4) = *(float4*)&Xs[k][tx * 8 + 4];
            #pragma unroll
            for (int i = 0; i < 8; i++)
                #pragma unroll
                for (int j = 0; j < 8; j++) acc[i][j] += a[i] * bb[j];
        }
        __syncthreads();
    }

    // per-thread row maxes over the 8 m-columns
    float rmax[8];
    #pragma unroll
    for (int i = 0; i < 8; i++) {
        float mx = acc[i][0];
        #pragma unroll
        for (int j = 1; j < 8; j++) mx = fmaxf(mx, acc[i][j]);
        rmax[i] = mx;
    }
    // reduce across the 16 tx lanes (same ty share rows; xor<16 stays in half-warp)
    #pragma unroll
    for (int off = 8; off >= 1; off >>= 1) {
        #pragma unroll
        for (int i = 0; i < 8; i++)
            rmax[i] = fmaxf(rmax[i], __shfl_xor_sync(0xFFFFFFFFu, rmax[i], off));
    }
    if (tx == 0) {
        #pragma unroll
        for (int i = 0; i < 8; i++)
            atomicMax(&g_m[b * NN + row0 + ty * 8 + i], float_ord(rmax[i]));
    }
}

// out[b][n][c] = SCALE * rowmax[b][c] * v[b][n]
__global__ void out_kernel(float* __restrict__ out) {
    size_t idx = (size_t)blockIdx.x * 256 + threadIdx.x;
    int c = (int)(idx & (NN - 1));
    size_t r = idx >> 11;
    int n = (int)(r & (NN - 1));
    int b = (int)(r >> 11);
    float m = ord_float(g_m[b * NN + c]);
    out[idx] = SCALE * m * g_v[b * NN + n];
}

extern "C" void kernel_launch(void* const* d_in, const int* in_sizes, int n_in,
                              void* d_out, int out_size) {
    const float* x  = (const float*)d_in[0];
    const float* Wq = (const float*)d_in[1];
    float* out = (float*)d_out;

    init_kernel<<<(NB * NN + 255) / 256, 256>>>();
    mean_kernel<<<dim3(NB, NN / 256, NN / 256), 256>>>(x);
    qgemm_kernel<<<dim3(NN / BN, NN / BM, NB), 256>>>(Wq, x);
    attn_max_kernel<<<dim3(NN / BN, NN / BM, NB), 256>>>(x);
    out_kernel<<<(int)(((size_t)NB * NN2) / 256), 256>>>(out);
}

// round 2
// speedup vs baseline: 1.9323x; 1.9323x over previous
#include <cuda_runtime.h>
#include <cuda_bf16.h>
#include <cstdint>

// Problem constants: B=8, N=C=2048, heads=8 -> scale = 1/16.
#define NB 8
#define NN 2048
#define NN2 (2048*2048)
#define SCALE 0.0625f

// ---------------- scratch (no cudaMalloc allowed) ----------------------------
__device__ __align__(256) __nv_bfloat16 g_qhi[(size_t)NB * NN2];
__device__ __align__(256) __nv_bfloat16 g_qlo[(size_t)NB * NN2];
__device__ __align__(256) __nv_bfloat16 g_xhi[(size_t)NB * NN2];   // x as-is (rows n, k=c)
__device__ __align__(256) __nv_bfloat16 g_xlo[(size_t)NB * NN2];
__device__ __align__(256) __nv_bfloat16 g_xthi[(size_t)NB * NN2];  // x transposed (rows c, k=n)
__device__ __align__(256) __nv_bfloat16 g_xtlo[(size_t)NB * NN2];
__device__ __align__(256) __nv_bfloat16 g_wqhi[NN2];
__device__ __align__(256) __nv_bfloat16 g_wqlo[NN2];
__device__ float        g_v[NB * NN];
__device__ unsigned int g_m[NB * NN];

// ---- monotone float<->uint order map (atomicMax over signed floats) ---------
__device__ __forceinline__ unsigned int float_ord(float f) {
    unsigned int u = __float_as_uint(f);
    return (u & 0x80000000u) ? ~u : (u | 0x80000000u);
}
__device__ __forceinline__ float ord_float(unsigned int o) {
    unsigned int u = (o & 0x80000000u) ? (o ^ 0x80000000u) : ~o;
    return __uint_as_float(u);
}

__device__ __forceinline__ void split2(float f, __nv_bfloat16& h, __nv_bfloat16& l) {
    h = __float2bfloat16(f);
    l = __float2bfloat16(f - __bfloat162float(h));
}

// ---- init -------------------------------------------------------------------
__global__ void init_kernel() {
    int i = blockIdx.x * 256 + threadIdx.x;
    if (i < NB * NN) { g_v[i] = 0.0f; g_m[i] = 0u; }
}

// ---- column means -----------------------------------------------------------
__global__ void mean_kernel(const float* __restrict__ x) {
    int b = blockIdx.x;
    int c = blockIdx.y * 256 + threadIdx.x;
    int n0 = blockIdx.z * 256;
    const float* xp = x + ((size_t)b * NN + n0) * NN + c;
    float s = 0.0f;
    #pragma unroll 8
    for (int n = 0; n < 256; n++) s += xp[(size_t)n * NN];
    atomicAdd(&g_v[b * NN + c], s * (1.0f / (float)NN));
}

// ---- fp32 -> bf16 hi/lo conversions -----------------------------------------
__global__ void convert_wq(const float* __restrict__ Wq) {
    size_t i = (size_t)blockIdx.x * 256 + threadIdx.x;
    float f = Wq[i];
    __nv_bfloat16 h, l; split2(f, h, l);
    g_wqhi[i] = h; g_wqlo[i] = l;
}

// x -> (x_hi, x_lo) same layout and (xt_hi, xt_lo) transposed, per batch.
__global__ void convert_x(const float* __restrict__ x) {
    __shared__ float t[32][33];
    int b = blockIdx.z;
    const float* xb = x + (size_t)b * NN2;
    int i0 = blockIdx.y * 32;   // row block (N axis)
    int l0 = blockIdx.x * 32;   // col block (C axis)
    int tx = threadIdx.x, ty = threadIdx.y;
    size_t bo = (size_t)b * NN2;
    #pragma unroll
    for (int ii = 0; ii < 4; ii++) {
        int r = ty + ii * 8;
        float f = xb[(size_t)(i0 + r) * NN + l0 + tx];
        __nv_bfloat16 h, l; split2(f, h, l);
        size_t o = bo + (size_t)(i0 + r) * NN + l0 + tx;
        g_xhi[o] = h; g_xlo[o] = l;
        t[r][tx] = f;
    }
    __syncthreads();
    #pragma unroll
    for (int ii = 0; ii < 4; ii++) {
        int r = ty + ii * 8;
        float f = t[tx][r];  // = xb[i0+tx][l0+r]
        __nv_bfloat16 h, l; split2(f, h, l);
        size_t o = bo + (size_t)(l0 + r) * NN + i0 + tx;
        g_xthi[o] = h; g_xtlo[o] = l;
    }
}

// ---------------- tensor-core GEMM (bf16x3, mma.sync m16n8k16) ---------------
// D = A * B^T where A rows are M (K-contig), B rows are N (K-contig).
// Block tile 128x128x32, 8 warps (4m x 2n), warp tile 32x64. 3-stage cp.async.
#define BM 128
#define BN 128
#define BKT 32
#define PADK 40                       // bf16 per smem row (32 data + 8 pad); 80B stride
#define ASZ (128 * PADK)              // elements per matrix per stage
#define STAGE_ELEMS (4 * ASZ)         // Ahi, Alo, Bhi, Blo
#define STAGE_BYTES (STAGE_ELEMS * 2)
#define NSTAGE 3
#define SMEM_BYTES (NSTAGE * STAGE_BYTES)   // 122880

__device__ __forceinline__ void ldsm4(uint32_t& d0, uint32_t& d1, uint32_t& d2,
                                      uint32_t& d3, uint32_t addr) {
    asm volatile("ldmatrix.sync.aligned.m8n8.x4.shared.b16 {%0,%1,%2,%3}, [%4];"
                 : "=r"(d0), "=r"(d1), "=r"(d2), "=r"(d3) : "r"(addr));
}
__device__ __forceinline__ void mma16816(float* c, const uint32_t* a, const uint32_t* b) {
    asm volatile(
        "mma.sync.aligned.m16n8k16.row.col.f32.bf16.bf16.f32 "
        "{%0,%1,%2,%3}, {%4,%5,%6,%7}, {%8,%9}, {%0,%1,%2,%3};"
        : "+f"(c[0]), "+f"(c[1]), "+f"(c[2]), "+f"(c[3])
        : "r"(a[0]), "r"(a[1]), "r"(a[2]), "r"(a[3]), "r"(b[0]), "r"(b[1]));
}
__device__ __forceinline__ void cp16(uint32_t dst, const void* src) {
    asm volatile("cp.async.cg.shared.global [%0], [%1], 16;" :: "r"(dst), "l"(src));
}

template<bool ROWMAX>
__global__ __launch_bounds__(256, 1) void mma_gemm(
    const __nv_bfloat16* __restrict__ Ahi, const __nv_bfloat16* __restrict__ Alo,
    const __nv_bfloat16* __restrict__ Bhi, const __nv_bfloat16* __restrict__ Blo,
    size_t aStride, size_t bStride,
    __nv_bfloat16* __restrict__ Chi, __nv_bfloat16* __restrict__ Clo)
{
    extern __shared__ __align__(16) __nv_bfloat16 smem[];
    const int tid  = threadIdx.x;
    const int lane = tid & 31;
    const int w    = tid >> 5;
    const int wm   = w >> 1;          // 0..3
    const int wn   = w & 1;           // 0..1
    const int b    = blockIdx.z;
    const int by   = blockIdx.y;      // M tile
    const int bx   = blockIdx.x;      // N tile

    const __nv_bfloat16* Ah = Ahi + (size_t)b * aStride;
    const __nv_bfloat16* Al = Alo + (size_t)b * aStride;
    const __nv_bfloat16* Bh = Bhi + (size_t)b * bStride;
    const __nv_bfloat16* Bl = Blo + (size_t)b * bStride;

    const uint32_t sbase = (uint32_t)__cvta_generic_to_shared(smem);

    // cp.async mapping: 512 16B-chunks per matrix; thread handles 2 per matrix
    const int cid0 = tid * 2;
    const int row_c0 = cid0 >> 2, chk_c0 = cid0 & 3;
    const int row_c1 = (cid0 + 1) >> 2, chk_c1 = (cid0 + 1) & 3;

    // ldmatrix address offsets
    const int rowoff = (lane & 7) + ((lane >> 3) & 1) * 8;
    const int koff   = (lane >> 4) * 8;

    float acc[2][8][4];
    #pragma unroll
    for (int i = 0; i < 2; i++)
        #pragma unroll
        for (int j = 0; j < 8; j++)
            #pragma unroll
            for (int k = 0; k < 4; k++) acc[i][j][k] = 0.0f;

    const __nv_bfloat16* mats[4] = { Ah, Al, Bh, Bl };
    const int rb[4] = { by * BM, by * BM, bx * BN, bx * BN };

    auto load_stage = [&](int kt, int s) {
        uint32_t sst = sbase + s * STAGE_BYTES;
        #pragma unroll
        for (int m = 0; m < 4; m++) {
            const __nv_bfloat16* g0 = mats[m] + (size_t)(rb[m] + row_c0) * NN + kt + chk_c0 * 8;
            const __nv_bfloat16* g1 = mats[m] + (size_t)(rb[m] + row_c1) * NN + kt + chk_c1 * 8;
            cp16(sst + m * (ASZ * 2) + (row_c0 * PADK + chk_c0 * 8) * 2, g0);
            cp16(sst + m * (ASZ * 2) + (row_c1 * PADK + chk_c1 * 8) * 2, g1);
        }
    };

    load_stage(0, 0);
    asm volatile("cp.async.commit_group;");
    load_stage(BKT, 1);
    asm volatile("cp.async.commit_group;");

    const int T = NN / BKT;   // 64
    for (int t = 0; t < T; t++) {
        asm volatile("cp.async.wait_group 1;");
        __syncthreads();
        if (t + 2 < T) load_stage((t + 2) * BKT, (t + 2) % NSTAGE);
        asm volatile("cp.async.commit_group;");

        uint32_t sA_hi = sbase + (t % NSTAGE) * STAGE_BYTES;
        uint32_t sA_lo = sA_hi + ASZ * 2;
        uint32_t sB_hi = sA_hi + 2 * ASZ * 2;
        uint32_t sB_lo = sA_hi + 3 * ASZ * 2;

        #pragma unroll
        for (int ks = 0; ks < 2; ks++) {
            const int kbase = ks * 16 + koff;
            uint32_t ah[2][4], al[2][4];
            #pragma unroll
            for (int mt = 0; mt < 2; mt++) {
                uint32_t off = ((wm * 32 + mt * 16 + rowoff) * PADK + kbase) * 2;
                ldsm4(ah[mt][0], ah[mt][1], ah[mt][2], ah[mt][3], sA_hi + off);
                ldsm4(al[mt][0], al[mt][1], al[mt][2], al[mt][3], sA_lo + off);
            }
            uint32_t bh[8][2], bl[8][2];
            #pragma unroll
            for (int nt2 = 0; nt2 < 4; nt2++) {
                uint32_t off = ((wn * 64 + nt2 * 16 + rowoff) * PADK + kbase) * 2;
                uint32_t d0, d1, d2, d3;
                ldsm4(d0, d1, d2, d3, sB_hi + off);
                bh[nt2 * 2][0] = d0; bh[nt2 * 2][1] = d2;
                bh[nt2 * 2 + 1][0] = d1; bh[nt2 * 2 + 1][1] = d3;
                ldsm4(d0, d1, d2, d3, sB_lo + off);
                bl[nt2 * 2][0] = d0; bl[nt2 * 2][1] = d2;
                bl[nt2 * 2 + 1][0] = d1; bl[nt2 * 2 + 1][1] = d3;
            }
            #pragma unroll
            for (int mt = 0; mt < 2; mt++)
                #pragma unroll
                for (int nt = 0; nt < 8; nt++) {
                    mma16816(acc[mt][nt], ah[mt], bh[nt]);
                    mma16816(acc[mt][nt], ah[mt], bl[nt]);
                    mma16816(acc[mt][nt], al[mt], bh[nt]);
                }
        }
    }

    if (!ROWMAX) {
        // store C split into hi/lo bf16 (q for gemm2)
        __nv_bfloat16* ch = Chi + (size_t)b * NN2;
        __nv_bfloat16* cl = Clo + (size_t)b * NN2;
        #pragma unroll
        for (int mt = 0; mt < 2; mt++) {
            int r0 = by * BM + wm * 32 + mt * 16 + (lane >> 2);
            #pragma unroll
            for (int nt = 0; nt < 8; nt++) {
                int c = bx * BN + wn * 64 + nt * 8 + (lane & 3) * 2;
                __nv_bfloat16 h0, l0, h1, l1;
                split2(acc[mt][nt][0], h0, l0);
                split2(acc[mt][nt][1], h1, l1);
                *(__nv_bfloat162*)(ch + (size_t)r0 * NN + c) = __nv_bfloat162(h0, h1);
                *(__nv_bfloat162*)(cl + (size_t)r0 * NN + c) = __nv_bfloat162(l0, l1);
                split2(acc[mt][nt][2], h0, l0);
                split2(acc[mt][nt][3], h1, l1);
                *(__nv_bfloat162*)(ch + (size_t)(r0 + 8) * NN + c) = __nv_bfloat162(h0, h1);
                *(__nv_bfloat162*)(cl + (size_t)(r0 + 8) * NN + c) = __nv_bfloat162(l0, l1);
            }
        }
    } else {
        // rowmax over the N dimension (attn's m axis), atomicMax into g_m
        #pragma unroll
        for (int mt = 0; mt < 2; mt++) {
            float m0 = -__int_as_float(0x7f800000), m1 = m0;
            #pragma unroll
            for (int nt = 0; nt < 8; nt++) {
                m0 = fmaxf(m0, fmaxf(acc[mt][nt][0], acc[mt][nt][1]));
                m1 = fmaxf(m1, fmaxf(acc[mt][nt][2], acc[mt][nt][3]));
            }
            m0 = fmaxf(m0, __shfl_xor_sync(0xFFFFFFFFu, m0, 1));
            m0 = fmaxf(m0, __shfl_xor_sync(0xFFFFFFFFu, m0, 2));
            m1 = fmaxf(m1, __shfl_xor_sync(0xFFFFFFFFu, m1, 1));
            m1 = fmaxf(m1, __shfl_xor_sync(0xFFFFFFFFu, m1, 2));
            if ((lane & 3) == 0) {
                int r0 = by * BM + wm * 32 + mt * 16 + (lane >> 2);
                atomicMax(&g_m[b * NN + r0], float_ord(m0));
                atomicMax(&g_m[b * NN + r0 + 8], float_ord(m1));
            }
        }
    }
}

// out[b][n][c] = SCALE * rowmax[b][c] * v[b][n]
__global__ void out_kernel(float* __restrict__ out) {
    size_t idx = (size_t)blockIdx.x * 256 + threadIdx.x;
    int c = (int)(idx & (NN - 1));
    size_t r = idx >> 11;
    int n = (int)(r & (NN - 1));
    int b = (int)(r >> 11);
    float m = ord_float(g_m[b * NN + c]);
    out[idx] = SCALE * m * g_v[b * NN + n];
}

extern "C" void kernel_launch(void* const* d_in, const int* in_sizes, int n_in,
                              void* d_out, int out_size) {
    const float* x  = (const float*)d_in[0];
    const float* Wq = (const float*)d_in[1];
    float* out = (float*)d_out;

    cudaFuncSetAttribute(mma_gemm<false>, cudaFuncAttributeMaxDynamicSharedMemorySize, SMEM_BYTES);
    cudaFuncSetAttribute(mma_gemm<true>,  cudaFuncAttributeMaxDynamicSharedMemorySize, SMEM_BYTES);

    init_kernel<<<(NB * NN + 255) / 256, 256>>>();
    mean_kernel<<<dim3(NB, NN / 256, NN / 256), 256>>>(x);
    convert_wq<<<NN2 / 256, 256>>>(Wq);
    convert_x<<<dim3(NN / 32, NN / 32, NB), dim3(32, 8)>>>(x);

    // GEMM1: q[n][c] = sum_i Wq[n][i] * xt[c][i]   (A=Wq batch-invariant, B=xT)
    __nv_bfloat16* wqh; cudaGetSymbolAddress((void**)&wqh, g_wqhi);
    __nv_bfloat16* wql; cudaGetSymbolAddress((void**)&wql, g_wqlo);
    __nv_bfloat16* xth; cudaGetSymbolAddress((void**)&xth, g_xthi);
    __nv_bfloat16* xtl; cudaGetSymbolAddress((void**)&xtl, g_xtlo);
    __nv_bfloat16* xh;  cudaGetSymbolAddress((void**)&xh,  g_xhi);
    __nv_bfloat16* xl;  cudaGetSymbolAddress((void**)&xl,  g_xlo);
    __nv_bfloat16* qh;  cudaGetSymbolAddress((void**)&qh,  g_qhi);
    __nv_bfloat16* ql;  cudaGetSymbolAddress((void**)&ql,  g_qlo);

    mma_gemm<false><<<dim3(NN / BN, NN / BM, NB), 256, SMEM_BYTES>>>(
        wqh, wql, xth, xtl, 0, (size_t)NN2, qh, ql);

    // GEMM2: attn[n][m] = sum_c q[n][c] * x[m][c], fused rowmax
    mma_gemm<true><<<dim3(NN / BN, NN / BM, NB), 256, SMEM_BYTES>>>(
        qh, ql, xh, xl, (size_t)NN2, (size_t)NN2, nullptr, nullptr);

    out_kernel<<<(int)(((size_t)NB * NN2) / 256), 256>>>(out);
}

// round 5
// speedup vs baseline: 2.2527x; 1.1658x over previous
#include <cuda_runtime.h>
#include <cuda_bf16.h>
#include <cstdint>

// B=8, N=C=2048, heads=8 -> scale = 1/16.
#define NB 8
#define NN 2048
#define NN2 (2048*2048)
#define SCALE 0.0625f

// ---------------- scratch ----------------------------------------------------
__device__ __align__(256) __nv_bfloat16 g_xhi[(size_t)NB * NN2];
__device__ __align__(256) __nv_bfloat16 g_xlo[(size_t)NB * NN2];
__device__ __align__(256) __nv_bfloat16 g_Ghi[(size_t)NB * NN2];
__device__ __align__(256) __nv_bfloat16 g_Glo[(size_t)NB * NN2];
__device__ __align__(256) __nv_bfloat16 g_wqhi[NN2];
__device__ __align__(256) __nv_bfloat16 g_wqlo[NN2];
__device__ float        g_v[NB * NN];
__device__ unsigned int g_m[NB * NN];

__device__ __forceinline__ unsigned int float_ord(float f) {
    unsigned int u = __float_as_uint(f);
    return (u & 0x80000000u) ? ~u : (u | 0x80000000u);
}
__device__ __forceinline__ float ord_float(unsigned int o) {
    unsigned int u = (o & 0x80000000u) ? (o ^ 0x80000000u) : ~o;
    return __uint_as_float(u);
}
__device__ __forceinline__ void split2(float f, __nv_bfloat16& h, __nv_bfloat16& l) {
    h = __float2bfloat16(f);
    l = __float2bfloat16(f - __bfloat162float(h));
}

// ---- small kernels ----------------------------------------------------------
__global__ void init_kernel() {
    int i = blockIdx.x * 256 + threadIdx.x;
    if (i < NB * NN) { g_v[i] = 0.0f; g_m[i] = 0u; }
}

__global__ void mean_kernel(const float* __restrict__ x) {
    int b = blockIdx.x;
    int c = blockIdx.y * 256 + threadIdx.x;
    int n0 = blockIdx.z * 256;
    const float* xp = x + ((size_t)b * NN + n0) * NN + c;
    float s = 0.0f;
    #pragma unroll 8
    for (int n = 0; n < 256; n++) s += xp[(size_t)n * NN];
    atomicAdd(&g_v[b * NN + c], s * (1.0f / (float)NN));
}

__global__ void convert_wq(const float* __restrict__ Wq) {
    size_t i = (size_t)blockIdx.x * 256 + threadIdx.x;
    float f = Wq[i];
    __nv_bfloat16 h, l; split2(f, h, l);
    g_wqhi[i] = h; g_wqlo[i] = l;
}

__global__ void convert_x(const float* __restrict__ x) {
    size_t g = (size_t)blockIdx.x * 256 + threadIdx.x;
    float4 f = ((const float4*)x)[g];
    __nv_bfloat16 h0,l0,h1,l1,h2,l2,h3,l3;
    split2(f.x,h0,l0); split2(f.y,h1,l1); split2(f.z,h2,l2); split2(f.w,h3,l3);
    ((__nv_bfloat162*)g_xhi)[g*2]   = __nv_bfloat162(h0,h1);
    ((__nv_bfloat162*)g_xhi)[g*2+1] = __nv_bfloat162(h2,h3);
    ((__nv_bfloat162*)g_xlo)[g*2]   = __nv_bfloat162(l0,l1);
    ((__nv_bfloat162*)g_xlo)[g*2+1] = __nv_bfloat162(l2,l3);
}

// ---------------- HMMA GEMM (mma.sync m16n8k16, folded bf16x3 K'=6144) -------
#define BM 128
#define BN 128
#define BKT 32
#define PADK 40                         // bf16 per smem row; 80B stride
#define A_BYTES (BM * PADK * 2)         // 10240
#define STG_BYTES (2 * A_BYTES)         // A + B per stage = 20480
#define NSTG 4
#define SMEM_BYTES (NSTG * STG_BYTES)   // 81920 (> 128*130*4 = 66560 epi buffer)
#define NTILES 192                      // 3 segments * 64 k-tiles
#define TFS 130                         // fp32 transpose buffer row stride (even!)

#define NMT 16                          // M tiles per batch row/col (2048/128)
#define NUT 136                         // upper-tri tile count

__device__ __forceinline__ void ldsm4(uint32_t& d0, uint32_t& d1, uint32_t& d2,
                                      uint32_t& d3, uint32_t addr) {
    asm volatile("ldmatrix.sync.aligned.m8n8.x4.shared.b16 {%0,%1,%2,%3}, [%4];"
                 : "=r"(d0), "=r"(d1), "=r"(d2), "=r"(d3) : "r"(addr));
}
__device__ __forceinline__ void mma16816(float* c, const uint32_t* a, const uint32_t* b) {
    asm volatile(
        "mma.sync.aligned.m16n8k16.row.col.f32.bf16.bf16.f32 "
        "{%0,%1,%2,%3}, {%4,%5,%6,%7}, {%8,%9}, {%0,%1,%2,%3};"
        : "+f"(c[0]), "+f"(c[1]), "+f"(c[2]), "+f"(c[3])
        : "r"(a[0]), "r"(a[1]), "r"(a[2]), "r"(a[3]), "r"(b[0]), "r"(b[1]));
}
__device__ __forceinline__ void cp16(uint32_t dst, const void* src) {
    asm volatile("cp.async.cg.shared.global [%0], [%1], 16;" :: "r"(dst), "l"(src));
}

// MODE 0: symmetric GEMM (G = A A^T upper tiles, write direct + transposed)
// MODE 1: GEMM with fused rowmax over N axis into g_m
template<int MODE>
__global__ __launch_bounds__(256, 1) void hgemm(
    const __nv_bfloat16* __restrict__ Ahi, const __nv_bfloat16* __restrict__ Alo,
    size_t aStride,
    const __nv_bfloat16* __restrict__ Bhi, const __nv_bfloat16* __restrict__ Blo,
    size_t bStride,
    __nv_bfloat16* __restrict__ Chi, __nv_bfloat16* __restrict__ Clo)
{
    extern __shared__ __align__(16) char smem[];
    const int tid  = threadIdx.x;
    const int lane = tid & 31;
    const int w    = tid >> 5;
    const int wm   = w >> 1;
    const int wn   = w & 1;
    const int b    = blockIdx.z;

    int by, bx;
    if (MODE == 0) {                 // decode upper-tri linear index
        int t = blockIdx.x, i = 0;
        while (t >= NMT - i) { t -= NMT - i; i++; }
        by = i; bx = i + t;
    } else {
        by = blockIdx.y; bx = blockIdx.x;
    }
    const int rowA = by * BM;
    const int rowB = bx * BN;

    const __nv_bfloat16* Ah = Ahi + (size_t)b * aStride;
    const __nv_bfloat16* Al = Alo + (size_t)b * aStride;
    const __nv_bfloat16* Bh = Bhi + (size_t)b * bStride;
    const __nv_bfloat16* Bl = Blo + (size_t)b * bStride;

    const uint32_t sbase = (uint32_t)__cvta_generic_to_shared(smem);

    // cp.async mapping: 512 16B-chunks per matrix / 256 threads = 2 each
    const int q0 = tid * 2, q1 = tid * 2 + 1;
    const int r0c = q0 >> 2, k0c = q0 & 3;
    const int r1c = q1 >> 2, k1c = q1 & 3;

    auto load_stage = [&](int tile) {
        uint32_t sb = sbase + (tile & (NSTG - 1)) * STG_BYTES;
        const int seg = tile >> 6;                 // 0,1,2
        const int kk  = (tile & 63) * BKT;
        const __nv_bfloat16* As = (seg < 2) ? Ah : Al;
        const __nv_bfloat16* Bs = (seg == 1) ? Bl : Bh;
        cp16(sb + r0c * 80 + k0c * 16, As + (size_t)(rowA + r0c) * NN + kk + k0c * 8);
        cp16(sb + r1c * 80 + k1c * 16, As + (size_t)(rowA + r1c) * NN + kk + k1c * 8);
        cp16(sb + A_BYTES + r0c * 80 + k0c * 16, Bs + (size_t)(rowB + r0c) * NN + kk + k0c * 8);
        cp16(sb + A_BYTES + r1c * 80 + k1c * 16, Bs + (size_t)(rowB + r1c) * NN + kk + k1c * 8);
    };

    const int rowoff = (lane & 7) + ((lane >> 3) & 1) * 8;
    const int koff   = (lane >> 4) * 8;

    float acc[2][8][4];
    #pragma unroll
    for (int i = 0; i < 2; i++)
        #pragma unroll
        for (int j = 0; j < 8; j++)
            #pragma unroll
            for (int k = 0; k < 4; k++) acc[i][j][k] = 0.0f;

    load_stage(0); asm volatile("cp.async.commit_group;");
    load_stage(1); asm volatile("cp.async.commit_group;");
    load_stage(2); asm volatile("cp.async.commit_group;");

    for (int t = 0; t < NTILES; t++) {
        asm volatile("cp.async.wait_group 2;");
        __syncthreads();
        if (t + 3 < NTILES) load_stage(t + 3);
        asm volatile("cp.async.commit_group;");

        uint32_t sA = sbase + (t & (NSTG - 1)) * STG_BYTES;
        uint32_t sB = sA + A_BYTES;
        #pragma unroll
        for (int ks = 0; ks < 2; ks++) {
            const int kbase = ks * 16 + koff;
            uint32_t a[2][4];
            #pragma unroll
            for (int mt = 0; mt < 2; mt++) {
                uint32_t off = ((wm * 32 + mt * 16 + rowoff) * PADK + kbase) * 2;
                ldsm4(a[mt][0], a[mt][1], a[mt][2], a[mt][3], sA + off);
            }
            uint32_t bb[8][2];
            #pragma unroll
            for (int nt2 = 0; nt2 < 4; nt2++) {
                uint32_t off = ((wn * 64 + nt2 * 16 + rowoff) * PADK + kbase) * 2;
                uint32_t d0, d1, d2, d3;
                ldsm4(d0, d1, d2, d3, sB + off);
                bb[nt2 * 2][0] = d0;     bb[nt2 * 2][1] = d2;
                bb[nt2 * 2 + 1][0] = d1; bb[nt2 * 2 + 1][1] = d3;
            }
            #pragma unroll
            for (int mt = 0; mt < 2; mt++)
                #pragma unroll
                for (int nt = 0; nt < 8; nt++)
                    mma16816(acc[mt][nt], a[mt], bb[nt]);
        }
    }
    asm volatile("cp.async.wait_group 0;");

    if (MODE == 0) {
        __nv_bfloat16* ch = Chi + (size_t)b * NN2;
        __nv_bfloat16* cl = Clo + (size_t)b * NN2;
        // direct store of tile (by,bx)
        #pragma unroll
        for (int mt = 0; mt < 2; mt++) {
            int r = rowA + wm * 32 + mt * 16 + (lane >> 2);
            #pragma unroll
            for (int nt = 0; nt < 8; nt++) {
                int c = rowB + wn * 64 + nt * 8 + (lane & 3) * 2;
                __nv_bfloat16 h0, l0, h1, l1;
                split2(acc[mt][nt][0], h0, l0);
                split2(acc[mt][nt][1], h1, l1);
                *(__nv_bfloat162*)(ch + (size_t)r * NN + c) = __nv_bfloat162(h0, h1);
                *(__nv_bfloat162*)(cl + (size_t)r * NN + c) = __nv_bfloat162(l0, l1);
                split2(acc[mt][nt][2], h0, l0);
                split2(acc[mt][nt][3], h1, l1);
                *(__nv_bfloat162*)(ch + (size_t)(r + 8) * NN + c) = __nv_bfloat162(h0, h1);
                *(__nv_bfloat162*)(cl + (size_t)(r + 8) * NN + c) = __nv_bfloat162(l0, l1);
            }
        }
        if (by != bx) {
            // stage fp32 tile in smem (row stride TFS=130 floats: float2-aligned
            // for every row), then write transposed
            float* tf = (float*)smem;
            __syncthreads();   // all warps done with pipeline smem
            #pragma unroll
            for (int mt = 0; mt < 2; mt++) {
                int rl = wm * 32 + mt * 16 + (lane >> 2);
                #pragma unroll
                for (int nt = 0; nt < 8; nt++) {
                    int clc = wn * 64 + nt * 8 + (lane & 3) * 2;
                    *(float2*)&tf[rl * TFS + clc]       = make_float2(acc[mt][nt][0], acc[mt][nt][1]);
                    *(float2*)&tf[(rl + 8) * TFS + clc] = make_float2(acc[mt][nt][2], acc[mt][nt][3]);
                }
            }
            __syncthreads();
            const int cc = tid >> 1;            // original col -> transposed row
            const int hh = (tid & 1) * 64;      // half of the 128 transposed cols
            __nv_bfloat16* chp = ch + (size_t)(rowB + cc) * NN + rowA + hh;
            __nv_bfloat16* clp = cl + (size_t)(rowB + cc) * NN + rowA + hh;
            #pragma unroll
            for (int g = 0; g < 8; g++) {
                __align__(16) __nv_bfloat16 hb[8], lb[8];
                #pragma unroll
                for (int e = 0; e < 8; e++)
                    split2(tf[(hh + g * 8 + e) * TFS + cc], hb[e], lb[e]);
                *(uint4*)(chp + g * 8) = *(uint4*)hb;
                *(uint4*)(clp + g * 8) = *(uint4*)lb;
            }
        }
    } else {
        // fused rowmax over the N axis
        #pragma unroll
        for (int mt = 0; mt < 2; mt++) {
            float m0 = -__int_as_float(0x7f800000), m1 = m0;
            #pragma unroll
            for (int nt = 0; nt < 8; nt++) {
                m0 = fmaxf(m0, fmaxf(acc[mt][nt][0], acc[mt][nt][1]));
                m1 = fmaxf(m1, fmaxf(acc[mt][nt][2], acc[mt][nt][3]));
            }
            m0 = fmaxf(m0, __shfl_xor_sync(0xFFFFFFFFu, m0, 1));
            m0 = fmaxf(m0, __shfl_xor_sync(0xFFFFFFFFu, m0, 2));
            m1 = fmaxf(m1, __shfl_xor_sync(0xFFFFFFFFu, m1, 1));
            m1 = fmaxf(m1, __shfl_xor_sync(0xFFFFFFFFu, m1, 2));
            if ((lane & 3) == 0) {
                int r = rowA + wm * 32 + mt * 16 + (lane >> 2);
                atomicMax(&g_m[b * NN + r], float_ord(m0));
                atomicMax(&g_m[b * NN + r + 8], float_ord(m1));
            }
        }
    }
}

// out[b][n][c] = SCALE * rowmax[b][c] * v[b][n]
__global__ void out_kernel(float* __restrict__ out) {
    size_t idx = (size_t)blockIdx.x * 256 + threadIdx.x;
    int c = (int)(idx & (NN - 1));
    size_t r = idx >> 11;
    int n = (int)(r & (NN - 1));
    int b = (int)(r >> 11);
    float m = ord_float(g_m[b * NN + c]);
    out[idx] = SCALE * m * g_v[b * NN + n];
}

extern "C" void kernel_launch(void* const* d_in, const int* in_sizes, int n_in,
                              void* d_out, int out_size) {
    const float* x  = (const float*)d_in[0];
    const float* Wq = (const float*)d_in[1];
    float* out = (float*)d_out;

    cudaFuncSetAttribute(hgemm<0>, cudaFuncAttributeMaxDynamicSharedMemorySize, SMEM_BYTES);
    cudaFuncSetAttribute(hgemm<1>, cudaFuncAttributeMaxDynamicSharedMemorySize, SMEM_BYTES);

    init_kernel<<<(NB * NN + 255) / 256, 256>>>();
    mean_kernel<<<dim3(NB, NN / 256, NN / 256), 256>>>(x);
    convert_wq<<<NN2 / 256, 256>>>(Wq);
    convert_x<<<(int)(((size_t)NB * NN2 / 4) / 256), 256>>>(x);

    __nv_bfloat16 *xh, *xl, *Gh, *Gl, *wh, *wl;
    cudaGetSymbolAddress((void**)&xh, g_xhi);
    cudaGetSymbolAddress((void**)&xl, g_xlo);
    cudaGetSymbolAddress((void**)&Gh, g_Ghi);
    cudaGetSymbolAddress((void**)&Gl, g_Glo);
    cudaGetSymbolAddress((void**)&wh, g_wqhi);
    cudaGetSymbolAddress((void**)&wl, g_wqlo);

    // GEMM1: G = x x^T, upper-triangular tiles only (G symmetric)
    hgemm<0><<<dim3(NUT, 1, NB), 256, SMEM_BYTES>>>(
        xh, xl, (size_t)NN2, xh, xl, (size_t)NN2, Gh, Gl);

    // GEMM2: attn = Wq G (rows of G are K-contig by symmetry), fused rowmax
    hgemm<1><<<dim3(NMT, NMT, NB), 256, SMEM_BYTES>>>(
        wh, wl, 0, Gh, Gl, (size_t)NN2, nullptr, nullptr);

    out_kernel<<<(int)(((size_t)NB * NN2) / 256), 256>>>(out);
}

// round 6
// speedup vs baseline: 2.3913x; 1.0615x over previous
#include <cuda_runtime.h>
#include <cuda_bf16.h>
#include <cstdint>

// B=8, N=C=2048, heads=8 -> scale = 1/16.
#define NB 8
#define NN 2048
#define NN2 (2048*2048)
#define SCALE 0.0625f

// ---------------- scratch ----------------------------------------------------
__device__ __align__(256) __nv_bfloat16 g_xhi[(size_t)NB * NN2];
__device__ __align__(256) __nv_bfloat16 g_xlo[(size_t)NB * NN2];
__device__ __align__(256) __nv_bfloat16 g_Ghi[(size_t)NB * NN2];
__device__ __align__(256) __nv_bfloat16 g_Glo[(size_t)NB * NN2];
__device__ __align__(256) __nv_bfloat16 g_wqhi[NN2];
__device__ __align__(256) __nv_bfloat16 g_wqlo[NN2];
__device__ float        g_v[NB * NN];
__device__ unsigned int g_m[NB * NN];

__device__ __forceinline__ unsigned int float_ord(float f) {
    unsigned int u = __float_as_uint(f);
    return (u & 0x80000000u) ? ~u : (u | 0x80000000u);
}
__device__ __forceinline__ float ord_float(unsigned int o) {
    unsigned int u = (o & 0x80000000u) ? (o ^ 0x80000000u) : ~o;
    return __uint_as_float(u);
}
__device__ __forceinline__ void split2(float f, __nv_bfloat16& h, __nv_bfloat16& l) {
    h = __float2bfloat16(f);
    l = __float2bfloat16(f - __bfloat162float(h));
}

// ---- small kernels ----------------------------------------------------------
__global__ void init_kernel() {
    int i = blockIdx.x * 256 + threadIdx.x;
    if (i < NB * NN) { g_v[i] = 0.0f; g_m[i] = 0u; }
}

__global__ void mean_kernel(const float* __restrict__ x) {
    int b = blockIdx.x;
    int c = blockIdx.y * 256 + threadIdx.x;
    int n0 = blockIdx.z * 256;
    const float* xp = x + ((size_t)b * NN + n0) * NN + c;
    float s = 0.0f;
    #pragma unroll 8
    for (int n = 0; n < 256; n++) s += xp[(size_t)n * NN];
    atomicAdd(&g_v[b * NN + c], s * (1.0f / (float)NN));
}

__global__ void convert_wq(const float* __restrict__ Wq) {
    size_t i = (size_t)blockIdx.x * 256 + threadIdx.x;
    float f = Wq[i];
    __nv_bfloat16 h, l; split2(f, h, l);
    g_wqhi[i] = h; g_wqlo[i] = l;
}

__global__ void convert_x(const float* __restrict__ x) {
    size_t g = (size_t)blockIdx.x * 256 + threadIdx.x;
    float4 f = ((const float4*)x)[g];
    __nv_bfloat16 h0,l0,h1,l1,h2,l2,h3,l3;
    split2(f.x,h0,l0); split2(f.y,h1,l1); split2(f.z,h2,l2); split2(f.w,h3,l3);
    ((__nv_bfloat162*)g_xhi)[g*2]   = __nv_bfloat162(h0,h1);
    ((__nv_bfloat162*)g_xhi)[g*2+1] = __nv_bfloat162(h2,h3);
    ((__nv_bfloat162*)g_xlo)[g*2]   = __nv_bfloat162(l0,l1);
    ((__nv_bfloat162*)g_xlo)[g*2+1] = __nv_bfloat162(l2,l3);
}

// ---------------- HMMA GEMM (mma.sync m16n8k16, folded bf16x3 K'=6144) -------
#define BM 128
#define BN 128
#define BKT 32
#define PADK 40                         // bf16 per smem row; 80B stride
#define A_BYTES (BM * PADK * 2)         // 10240
#define STG_BYTES (2 * A_BYTES)         // A + B per stage = 20480
#define NSTG 4
#define SMEM_BYTES (NSTG * STG_BYTES)   // 81920 (> 128*130*4 = 66560 epi buffer)
#define NTILES 192                      // 3 segments * 64 k-tiles
#define TFS 130                         // fp32 transpose buffer row stride (even!)

#define NMT 16                          // M tiles per batch row/col (2048/128)
#define NUT 136                         // upper-tri tile count

__device__ __forceinline__ void ldsm4(uint32_t& d0, uint32_t& d1, uint32_t& d2,
                                      uint32_t& d3, uint32_t addr) {
    asm volatile("ldmatrix.sync.aligned.m8n8.x4.shared.b16 {%0,%1,%2,%3}, [%4];"
                 : "=r"(d0), "=r"(d1), "=r"(d2), "=r"(d3) : "r"(addr));
}
__device__ __forceinline__ void mma16816(float* c, const uint32_t* a, const uint32_t* b) {
    asm volatile(
        "mma.sync.aligned.m16n8k16.row.col.f32.bf16.bf16.f32 "
        "{%0,%1,%2,%3}, {%4,%5,%6,%7}, {%8,%9}, {%0,%1,%2,%3};"
        : "+f"(c[0]), "+f"(c[1]), "+f"(c[2]), "+f"(c[3])
        : "r"(a[0]), "r"(a[1]), "r"(a[2]), "r"(a[3]), "r"(b[0]), "r"(b[1]));
}
__device__ __forceinline__ void cp16(uint32_t dst, const void* src) {
    asm volatile("cp.async.cg.shared.global [%0], [%1], 16;" :: "r"(dst), "l"(src));
}

// MODE 0: symmetric GEMM (G = A A^T upper tiles, write direct + transposed)
// MODE 1: GEMM with fused rowmax over N axis into g_m
template<int MODE>
__global__ __launch_bounds__(256, 2) void hgemm(
    const __nv_bfloat16* __restrict__ Ahi, const __nv_bfloat16* __restrict__ Alo,
    size_t aStride,
    const __nv_bfloat16* __restrict__ Bhi, const __nv_bfloat16* __restrict__ Blo,
    size_t bStride,
    __nv_bfloat16* __restrict__ Chi, __nv_bfloat16* __restrict__ Clo)
{
    extern __shared__ __align__(16) char smem[];
    const int tid  = threadIdx.x;
    const int lane = tid & 31;
    const int w    = tid >> 5;
    const int wm   = w >> 1;
    const int wn   = w & 1;
    const int b    = blockIdx.z;

    int by, bx;
    if (MODE == 0) {                 // decode upper-tri linear index
        int t = blockIdx.x, i = 0;
        while (t >= NMT - i) { t -= NMT - i; i++; }
        by = i; bx = i + t;
    } else {
        by = blockIdx.y; bx = blockIdx.x;
    }
    const int rowA = by * BM;
    const int rowB = bx * BN;

    const __nv_bfloat16* Ah = Ahi + (size_t)b * aStride;
    const __nv_bfloat16* Al = Alo + (size_t)b * aStride;
    const __nv_bfloat16* Bh = Bhi + (size_t)b * bStride;
    const __nv_bfloat16* Bl = Blo + (size_t)b * bStride;

    const uint32_t sbase = (uint32_t)__cvta_generic_to_shared(smem);

    // cp.async mapping: 512 16B-chunks per matrix / 256 threads = 2 each
    const int q0 = tid * 2, q1 = tid * 2 + 1;
    const int r0c = q0 >> 2, k0c = q0 & 3;
    const int r1c = q1 >> 2, k1c = q1 & 3;

    auto load_stage = [&](int tile) {
        uint32_t sb = sbase + (tile & (NSTG - 1)) * STG_BYTES;
        const int seg = tile >> 6;                 // 0,1,2
        const int kk  = (tile & 63) * BKT;
        const __nv_bfloat16* As = (seg < 2) ? Ah : Al;
        const __nv_bfloat16* Bs = (seg == 1) ? Bl : Bh;
        cp16(sb + r0c * 80 + k0c * 16, As + (size_t)(rowA + r0c) * NN + kk + k0c * 8);
        cp16(sb + r1c * 80 + k1c * 16, As + (size_t)(rowA + r1c) * NN + kk + k1c * 8);
        cp16(sb + A_BYTES + r0c * 80 + k0c * 16, Bs + (size_t)(rowB + r0c) * NN + kk + k0c * 8);
        cp16(sb + A_BYTES + r1c * 80 + k1c * 16, Bs + (size_t)(rowB + r1c) * NN + kk + k1c * 8);
    };

    const int rowoff = (lane & 7) + ((lane >> 3) & 1) * 8;
    const int koff   = (lane >> 4) * 8;

    float acc[2][8][4];
    #pragma unroll
    for (int i = 0; i < 2; i++)
        #pragma unroll
        for (int j = 0; j < 8; j++)
            #pragma unroll
            for (int k = 0; k < 4; k++) acc[i][j][k] = 0.0f;

    load_stage(0); asm volatile("cp.async.commit_group;");
    load_stage(1); asm volatile("cp.async.commit_group;");
    load_stage(2); asm volatile("cp.async.commit_group;");

    for (int t = 0; t < NTILES; t++) {
        asm volatile("cp.async.wait_group 2;");
        __syncthreads();
        if (t + 3 < NTILES) load_stage(t + 3);
        asm volatile("cp.async.commit_group;");

        uint32_t sA = sbase + (t & (NSTG - 1)) * STG_BYTES;
        uint32_t sB = sA + A_BYTES;
        #pragma unroll
        for (int ks = 0; ks < 2; ks++) {
            const int kbase = ks * 16 + koff;
            uint32_t a[2][4];
            #pragma unroll
            for (int mt = 0; mt < 2; mt++) {
                uint32_t off = ((wm * 32 + mt * 16 + rowoff) * PADK + kbase) * 2;
                ldsm4(a[mt][0], a[mt][1], a[mt][2], a[mt][3], sA + off);
            }
            uint32_t bb[8][2];
            #pragma unroll
            for (int nt2 = 0; nt2 < 4; nt2++) {
                uint32_t off = ((wn * 64 + nt2 * 16 + rowoff) * PADK + kbase) * 2;
                uint32_t d0, d1, d2, d3;
                ldsm4(d0, d1, d2, d3, sB + off);
                bb[nt2 * 2][0] = d0;     bb[nt2 * 2][1] = d2;
                bb[nt2 * 2 + 1][0] = d1; bb[nt2 * 2 + 1][1] = d3;
            }
            #pragma unroll
            for (int mt = 0; mt < 2; mt++)
                #pragma unroll
                for (int nt = 0; nt < 8; nt++)
                    mma16816(acc[mt][nt], a[mt], bb[nt]);
        }
    }
    asm volatile("cp.async.wait_group 0;");

    if (MODE == 0) {
        __nv_bfloat16* ch = Chi + (size_t)b * NN2;
        __nv_bfloat16* cl = Clo + (size_t)b * NN2;
        // direct store of tile (by,bx)
        #pragma unroll
        for (int mt = 0; mt < 2; mt++) {
            int r = rowA + wm * 32 + mt * 16 + (lane >> 2);
            #pragma unroll
            for (int nt = 0; nt < 8; nt++) {
                int c = rowB + wn * 64 + nt * 8 + (lane & 3) * 2;
                __nv_bfloat16 h0, l0, h1, l1;
                split2(acc[mt][nt][0], h0, l0);
                split2(acc[mt][nt][1], h1, l1);
                *(__nv_bfloat162*)(ch + (size_t)r * NN + c) = __nv_bfloat162(h0, h1);
                *(__nv_bfloat162*)(cl + (size_t)r * NN + c) = __nv_bfloat162(l0, l1);
                split2(acc[mt][nt][2], h0, l0);
                split2(acc[mt][nt][3], h1, l1);
                *(__nv_bfloat162*)(ch + (size_t)(r + 8) * NN + c) = __nv_bfloat162(h0, h1);
                *(__nv_bfloat162*)(cl + (size_t)(r + 8) * NN + c) = __nv_bfloat162(l0, l1);
            }
        }
        if (by != bx) {
            // stage fp32 tile in smem (row stride TFS=130 floats: float2-aligned
            // for every row), then write transposed
            float* tf = (float*)smem;
            __syncthreads();   // all warps done with pipeline smem
            #pragma unroll
            for (int mt = 0; mt < 2; mt++) {
                int rl = wm * 32 + mt * 16 + (lane >> 2);
                #pragma unroll
                for (int nt = 0; nt < 8; nt++) {
                    int clc = wn * 64 + nt * 8 + (lane & 3) * 2;
                    *(float2*)&tf[rl * TFS + clc]       = make_float2(acc[mt][nt][0], acc[mt][nt][1]);
                    *(float2*)&tf[(rl + 8) * TFS + clc] = make_float2(acc[mt][nt][2], acc[mt][nt][3]);
                }
            }
            __syncthreads();
            const int cc = tid >> 1;            // original col -> transposed row
            const int hh = (tid & 1) * 64;      // half of the 128 transposed cols
            __nv_bfloat16* chp = ch + (size_t)(rowB + cc) * NN + rowA + hh;
            __nv_bfloat16* clp = cl + (size_t)(rowB + cc) * NN + rowA + hh;
            #pragma unroll
            for (int g = 0; g < 8; g++) {
                __align__(16) __nv_bfloat16 hb[8], lb[8];
                #pragma unroll
                for (int e = 0; e < 8; e++)
                    split2(tf[(hh + g * 8 + e) * TFS + cc], hb[e], lb[e]);
                *(uint4*)(chp + g * 8) = *(uint4*)hb;
                *(uint4*)(clp + g * 8) = *(uint4*)lb;
            }
        }
    } else {
        // fused rowmax over the N axis
        #pragma unroll
        for (int mt = 0; mt < 2; mt++) {
            float m0 = -__int_as_float(0x7f800000), m1 = m0;
            #pragma unroll
            for (int nt = 0; nt < 8; nt++) {
                m0 = fmaxf(m0, fmaxf(acc[mt][nt][0], acc[mt][nt][1]));
                m1 = fmaxf(m1, fmaxf(acc[mt][nt][2], acc[mt][nt][3]));
            }
            m0 = fmaxf(m0, __shfl_xor_sync(0xFFFFFFFFu, m0, 1));
            m0 = fmaxf(m0, __shfl_xor_sync(0xFFFFFFFFu, m0, 2));
            m1 = fmaxf(m1, __shfl_xor_sync(0xFFFFFFFFu, m1, 1));
            m1 = fmaxf(m1, __shfl_xor_sync(0xFFFFFFFFu, m1, 2));
            if ((lane & 3) == 0) {
                int r = rowA + wm * 32 + mt * 16 + (lane >> 2);
                atomicMax(&g_m[b * NN + r], float_ord(m0));
                atomicMax(&g_m[b * NN + r + 8], float_ord(m1));
            }
        }
    }
}

// out[b][n][c] = SCALE * rowmax[b][c] * v[b][n]
__global__ void out_kernel(float* __restrict__ out) {
    size_t idx = (size_t)blockIdx.x * 256 + threadIdx.x;
    int c = (int)(idx & (NN - 1));
    size_t r = idx >> 11;
    int n = (int)(r & (NN - 1));
    int b = (int)(r >> 11);
    float m = ord_float(g_m[b * NN + c]);
    out[idx] = SCALE * m * g_v[b * NN + n];
}

extern "C" void kernel_launch(void* const* d_in, const int* in_sizes, int n_in,
                              void* d_out, int out_size) {
    const float* x  = (const float*)d_in[0];
    const float* Wq = (const float*)d_in[1];
    float* out = (float*)d_out;

    cudaFuncSetAttribute(hgemm<0>, cudaFuncAttributeMaxDynamicSharedMemorySize, SMEM_BYTES);
    cudaFuncSetAttribute(hgemm<1>, cudaFuncAttributeMaxDynamicSharedMemorySize, SMEM_BYTES);

    init_kernel<<<(NB * NN + 255) / 256, 256>>>();
    mean_kernel<<<dim3(NB, NN / 256, NN / 256), 256>>>(x);
    convert_wq<<<NN2 / 256, 256>>>(Wq);
    convert_x<<<(int)(((size_t)NB * NN2 / 4) / 256), 256>>>(x);

    __nv_bfloat16 *xh, *xl, *Gh, *Gl, *wh, *wl;
    cudaGetSymbolAddress((void**)&xh, g_xhi);
    cudaGetSymbolAddress((void**)&xl, g_xlo);
    cudaGetSymbolAddress((void**)&Gh, g_Ghi);
    cudaGetSymbolAddress((void**)&Gl, g_Glo);
    cudaGetSymbolAddress((void**)&wh, g_wqhi);
    cudaGetSymbolAddress((void**)&wl, g_wqlo);

    // GEMM1: G = x x^T, upper-triangular tiles only (G symmetric)
    hgemm<0><<<dim3(NUT, 1, NB), 256, SMEM_BYTES>>>(
        xh, xl, (size_t)NN2, xh, xl, (size_t)NN2, Gh, Gl);

    // GEMM2: attn = Wq G (rows of G are K-contig by symmetry), fused rowmax
    hgemm<1><<<dim3(NMT, NMT, NB), 256, SMEM_BYTES>>>(
        wh, wl, 0, Gh, Gl, (size_t)NN2, nullptr, nullptr);

    out_kernel<<<(int)(((size_t)NB * NN2) / 256), 256>>>(out);
}

// round 7
// speedup vs baseline: 2.9736x; 1.2435x over previous
#include <cuda_runtime.h>
#include <cuda_bf16.h>
#include <cstdint>

// B=8, N=C=2048, heads=8 -> scale = 1/16.
#define NB 8
#define NN 2048
#define NN2 (2048*2048)
#define SCALE 0.0625f

// ---------------- scratch ----------------------------------------------------
__device__ __align__(256) __nv_bfloat16 g_xhi[(size_t)NB * NN2];
__device__ __align__(256) __nv_bfloat16 g_xlo[(size_t)NB * NN2];
__device__ __align__(256) __nv_bfloat16 g_Ghi[(size_t)NB * NN2];
__device__ __align__(256) __nv_bfloat16 g_Glo[(size_t)NB * NN2];
__device__ __align__(256) __nv_bfloat16 g_wqhi[NN2];
__device__ __align__(256) float         g_attn[(size_t)NB * NN2];  // approx attn fp32
__device__ float g_v[NB * NN];      // column means of x
__device__ float g_m[NB * NN];      // final row maxes (exact, written by repair)
__device__ float g_wn[NN];          // ||Wq row n||2  (fp32)
__device__ float g_wln[NN];         // ||Wq row n - bf16(Wq row n)||2
__device__ unsigned int g_gnh[NB];  // max_m ||Gh col m||2  (as ordered uint, positive)
__device__ unsigned int g_gnl[NB];  // max_m ||Gl col m||2

__device__ __forceinline__ void split2(float f, __nv_bfloat16& h, __nv_bfloat16& l) {
    h = __float2bfloat16(f);
    l = __float2bfloat16(f - __bfloat162float(h));
}

// ---- small kernels ----------------------------------------------------------
__global__ void init_kernel() {
    int i = blockIdx.x * 256 + threadIdx.x;
    if (i < NB * NN) g_v[i] = 0.0f;
    if (i < NB) { g_gnh[i] = 0u; g_gnl[i] = 0u; }
}

__global__ void mean_kernel(const float* __restrict__ x) {
    int b = blockIdx.x;
    int c = blockIdx.y * 256 + threadIdx.x;
    int n0 = blockIdx.z * 256;
    const float* xp = x + ((size_t)b * NN + n0) * NN + c;
    float s = 0.0f;
    #pragma unroll 8
    for (int n = 0; n < 256; n++) s += xp[(size_t)n * NN];
    atomicAdd(&g_v[b * NN + c], s * (1.0f / (float)NN));
}

// Wq -> bf16 hi; also per-row norms of Wq and of the bf16 residual.
__global__ void convert_wq(const float* __restrict__ Wq) {
    __shared__ float sw[256], sl[256];
    int n = blockIdx.x;
    int t = threadIdx.x;
    float ssw = 0.0f, ssl = 0.0f;
    #pragma unroll
    for (int j = 0; j < 8; j++) {
        int i = t * 8 + j;
        float f = Wq[(size_t)n * NN + i];
        __nv_bfloat16 h = __float2bfloat16(f);
        g_wqhi[(size_t)n * NN + i] = h;
        float r = f - __bfloat162float(h);
        ssw += f * f; ssl += r * r;
    }
    sw[t] = ssw; sl[t] = ssl;
    __syncthreads();
    for (int s = 128; s > 0; s >>= 1) {
        if (t < s) { sw[t] += sw[t + s]; sl[t] += sl[t + s]; }
        __syncthreads();
    }
    if (t == 0) { g_wn[n] = sqrtf(sw[0]); g_wln[n] = sqrtf(sl[0]); }
}

__global__ void convert_x(const float* __restrict__ x) {
    size_t g = (size_t)blockIdx.x * 256 + threadIdx.x;
    float4 f = ((const float4*)x)[g];
    __nv_bfloat16 h0,l0,h1,l1,h2,l2,h3,l3;
    split2(f.x,h0,l0); split2(f.y,h1,l1); split2(f.z,h2,l2); split2(f.w,h3,l3);
    ((__nv_bfloat162*)g_xhi)[g*2]   = __nv_bfloat162(h0,h1);
    ((__nv_bfloat162*)g_xhi)[g*2+1] = __nv_bfloat162(h2,h3);
    ((__nv_bfloat162*)g_xlo)[g*2]   = __nv_bfloat162(l0,l1);
    ((__nv_bfloat162*)g_xlo)[g*2+1] = __nv_bfloat162(l2,l3);
}

// per-row (== per-col, symmetric) norms of Gh and Gl; keep per-batch max.
__global__ void gnorm_kernel() {
    __shared__ float sh[256], slo[256];
    int b = blockIdx.y;
    int m = blockIdx.x;
    int t = threadIdx.x;
    const __nv_bfloat16* gh = g_Ghi + (size_t)b * NN2 + (size_t)m * NN;
    const __nv_bfloat16* gl = g_Glo + (size_t)b * NN2 + (size_t)m * NN;
    float s1 = 0.0f, s2 = 0.0f;
    #pragma unroll
    for (int j = 0; j < 8; j++) {
        float a = __bfloat162float(gh[t * 8 + j]);
        float c = __bfloat162float(gl[t * 8 + j]);
        s1 += a * a; s2 += c * c;
    }
    sh[t] = s1; slo[t] = s2;
    __syncthreads();
    for (int s = 128; s > 0; s >>= 1) {
        if (t < s) { sh[t] += sh[t + s]; slo[t] += slo[t + s]; }
        __syncthreads();
    }
    if (t == 0) {
        atomicMax(&g_gnh[b], __float_as_uint(sqrtf(sh[0])));
        atomicMax(&g_gnl[b], __float_as_uint(sqrtf(slo[0])));
    }
}

// ---------------- HMMA GEMM (mma.sync m16n8k16) ------------------------------
#define BM 128
#define BN 128
#define BKT 32
#define PADK 40
#define A_BYTES (BM * PADK * 2)         // 10240
#define STG_BYTES (2 * A_BYTES)
#define NSTG 4
#define SMEM_BYTES (NSTG * STG_BYTES)   // 81920
#define TFS 130

#define NMT 16
#define NUT 136

__device__ __forceinline__ void ldsm4(uint32_t& d0, uint32_t& d1, uint32_t& d2,
                                      uint32_t& d3, uint32_t addr) {
    asm volatile("ldmatrix.sync.aligned.m8n8.x4.shared.b16 {%0,%1,%2,%3}, [%4];"
                 : "=r"(d0), "=r"(d1), "=r"(d2), "=r"(d3) : "r"(addr));
}
__device__ __forceinline__ void mma16816(float* c, const uint32_t* a, const uint32_t* b) {
    asm volatile(
        "mma.sync.aligned.m16n8k16.row.col.f32.bf16.bf16.f32 "
        "{%0,%1,%2,%3}, {%4,%5,%6,%7}, {%8,%9}, {%0,%1,%2,%3};"
        : "+f"(c[0]), "+f"(c[1]), "+f"(c[2]), "+f"(c[3])
        : "r"(a[0]), "r"(a[1]), "r"(a[2]), "r"(a[3]), "r"(b[0]), "r"(b[1]));
}
__device__ __forceinline__ void cp16(uint32_t dst, const void* src) {
    asm volatile("cp.async.cg.shared.global [%0], [%1], 16;" :: "r"(dst), "l"(src));
}

// MODE 0: symmetric bf16x3 GEMM (G = A A^T upper tiles, write direct + transposed)
// MODE 2: single-pass GEMM (Ah*Bh^T), fp32 tile store to Cf
template<int MODE>
__global__ __launch_bounds__(256, 2) void hgemm(
    const __nv_bfloat16* __restrict__ Ahi, const __nv_bfloat16* __restrict__ Alo,
    size_t aStride,
    const __nv_bfloat16* __restrict__ Bhi, const __nv_bfloat16* __restrict__ Blo,
    size_t bStride,
    __nv_bfloat16* __restrict__ Chi, __nv_bfloat16* __restrict__ Clo,
    float* __restrict__ Cf)
{
    extern __shared__ __align__(16) char smem[];
    const int tid  = threadIdx.x;
    const int lane = tid & 31;
    const int w    = tid >> 5;
    const int wm   = w >> 1;
    const int wn   = w & 1;
    const int b    = blockIdx.z;
    constexpr int NT = (MODE == 0) ? 192 : 64;   // 3 segs vs 1 seg of 64 k-tiles

    int by, bx;
    if (MODE == 0) {
        int t = blockIdx.x, i = 0;
        while (t >= NMT - i) { t -= NMT - i; i++; }
        by = i; bx = i + t;
    } else {
        by = blockIdx.y; bx = blockIdx.x;
    }
    const int rowA = by * BM;
    const int rowB = bx * BN;

    const __nv_bfloat16* Ah = Ahi + (size_t)b * aStride;
    const __nv_bfloat16* Al = Alo + (size_t)b * aStride;
    const __nv_bfloat16* Bh = Bhi + (size_t)b * bStride;
    const __nv_bfloat16* Bl = Blo + (size_t)b * bStride;

    const uint32_t sbase = (uint32_t)__cvta_generic_to_shared(smem);

    const int q0 = tid * 2, q1 = tid * 2 + 1;
    const int r0c = q0 >> 2, k0c = q0 & 3;
    const int r1c = q1 >> 2, k1c = q1 & 3;

    auto load_stage = [&](int tile) {
        uint32_t sb = sbase + (tile & (NSTG - 1)) * STG_BYTES;
        const __nv_bfloat16* As;
        const __nv_bfloat16* Bs;
        int kk;
        if (MODE == 0) {
            const int seg = tile >> 6;
            kk = (tile & 63) * BKT;
            As = (seg < 2) ? Ah : Al;
            Bs = (seg == 1) ? Bl : Bh;
        } else {
            kk = tile * BKT;
            As = Ah; Bs = Bh;
        }
        cp16(sb + r0c * 80 + k0c * 16, As + (size_t)(rowA + r0c) * NN + kk + k0c * 8);
        cp16(sb + r1c * 80 + k1c * 16, As + (size_t)(rowA + r1c) * NN + kk + k1c * 8);
        cp16(sb + A_BYTES + r0c * 80 + k0c * 16, Bs + (size_t)(rowB + r0c) * NN + kk + k0c * 8);
        cp16(sb + A_BYTES + r1c * 80 + k1c * 16, Bs + (size_t)(rowB + r1c) * NN + kk + k1c * 8);
    };

    const int rowoff = (lane & 7) + ((lane >> 3) & 1) * 8;
    const int koff   = (lane >> 4) * 8;

    float acc[2][8][4];
    #pragma unroll
    for (int i = 0; i < 2; i++)
        #pragma unroll
        for (int j = 0; j < 8; j++)
            #pragma unroll
            for (int k = 0; k < 4; k++) acc[i][j][k] = 0.0f;

    load_stage(0); asm volatile("cp.async.commit_group;");
    load_stage(1); asm volatile("cp.async.commit_group;");
    load_stage(2); asm volatile("cp.async.commit_group;");

    for (int t = 0; t < NT; t++) {
        asm volatile("cp.async.wait_group 2;");
        __syncthreads();
        if (t + 3 < NT) load_stage(t + 3);
        asm volatile("cp.async.commit_group;");

        uint32_t sA = sbase + (t & (NSTG - 1)) * STG_BYTES;
        uint32_t sB = sA + A_BYTES;
        #pragma unroll
        for (int ks = 0; ks < 2; ks++) {
            const int kbase = ks * 16 + koff;
            uint32_t a[2][4];
            #pragma unroll
            for (int mt = 0; mt < 2; mt++) {
                uint32_t off = ((wm * 32 + mt * 16 + rowoff) * PADK + kbase) * 2;
                ldsm4(a[mt][0], a[mt][1], a[mt][2], a[mt][3], sA + off);
            }
            uint32_t bb[8][2];
            #pragma unroll
            for (int nt2 = 0; nt2 < 4; nt2++) {
                uint32_t off = ((wn * 64 + nt2 * 16 + rowoff) * PADK + kbase) * 2;
                uint32_t d0, d1, d2, d3;
                ldsm4(d0, d1, d2, d3, sB + off);
                bb[nt2 * 2][0] = d0;     bb[nt2 * 2][1] = d2;
                bb[nt2 * 2 + 1][0] = d1; bb[nt2 * 2 + 1][1] = d3;
            }
            #pragma unroll
            for (int mt = 0; mt < 2; mt++)
                #pragma unroll
                for (int nt = 0; nt < 8; nt++)
                    mma16816(acc[mt][nt], a[mt], bb[nt]);
        }
    }
    asm volatile("cp.async.wait_group 0;");

    if (MODE == 0) {
        __nv_bfloat16* ch = Chi + (size_t)b * NN2;
        __nv_bfloat16* cl = Clo + (size_t)b * NN2;
        #pragma unroll
        for (int mt = 0; mt < 2; mt++) {
            int r = rowA + wm * 32 + mt * 16 + (lane >> 2);
            #pragma unroll
            for (int nt = 0; nt < 8; nt++) {
                int c = rowB + wn * 64 + nt * 8 + (lane & 3) * 2;
                __nv_bfloat16 h0, l0, h1, l1;
                split2(acc[mt][nt][0], h0, l0);
                split2(acc[mt][nt][1], h1, l1);
                *(__nv_bfloat162*)(ch + (size_t)r * NN + c) = __nv_bfloat162(h0, h1);
                *(__nv_bfloat162*)(cl + (size_t)r * NN + c) = __nv_bfloat162(l0, l1);
                split2(acc[mt][nt][2], h0, l0);
                split2(acc[mt][nt][3], h1, l1);
                *(__nv_bfloat162*)(ch + (size_t)(r + 8) * NN + c) = __nv_bfloat162(h0, h1);
                *(__nv_bfloat162*)(cl + (size_t)(r + 8) * NN + c) = __nv_bfloat162(l0, l1);
            }
        }
        if (by != bx) {
            float* tf = (float*)smem;
            __syncthreads();
            #pragma unroll
            for (int mt = 0; mt < 2; mt++) {
                int rl = wm * 32 + mt * 16 + (lane >> 2);
                #pragma unroll
                for (int nt = 0; nt < 8; nt++) {
                    int clc = wn * 64 + nt * 8 + (lane & 3) * 2;
                    *(float2*)&tf[rl * TFS + clc]       = make_float2(acc[mt][nt][0], acc[mt][nt][1]);
                    *(float2*)&tf[(rl + 8) * TFS + clc] = make_float2(acc[mt][nt][2], acc[mt][nt][3]);
                }
            }
            __syncthreads();
            const int cc = tid >> 1;
            const int hh = (tid & 1) * 64;
            __nv_bfloat16* chp = ch + (size_t)(rowB + cc) * NN + rowA + hh;
            __nv_bfloat16* clp = cl + (size_t)(rowB + cc) * NN + rowA + hh;
            #pragma unroll
            for (int g = 0; g < 8; g++) {
                __align__(16) __nv_bfloat16 hb[8], lb[8];
                #pragma unroll
                for (int e = 0; e < 8; e++)
                    split2(tf[(hh + g * 8 + e) * TFS + cc], hb[e], lb[e]);
                *(uint4*)(chp + g * 8) = *(uint4*)hb;
                *(uint4*)(clp + g * 8) = *(uint4*)lb;
            }
        }
    } else {
        // fp32 tile store of approx attn
        float* ga = Cf + (size_t)b * NN2;
        #pragma unroll
        for (int mt = 0; mt < 2; mt++) {
            int r = rowA + wm * 32 + mt * 16 + (lane >> 2);
            #pragma unroll
            for (int nt = 0; nt < 8; nt++) {
                int c = rowB + wn * 64 + nt * 8 + (lane & 3) * 2;
                *(float2*)(ga + (size_t)r * NN + c)       = make_float2(acc[mt][nt][0], acc[mt][nt][1]);
                *(float2*)(ga + (size_t)(r + 8) * NN + c) = make_float2(acc[mt][nt][2], acc[mt][nt][3]);
            }
        }
    }
}

// ---- candidate selection + exact repair -------------------------------------
// One warp per (b, n) row. Scan approx attn row, pick candidates within 2*bound
// of the approx max, recompute those entries exactly in fp32, write exact max.
#define MAXCAND 128
__global__ void repair_kernel(const float* __restrict__ Wq) {
    __shared__ int s_cand[8][MAXCAND];
    __shared__ int s_cnt[8];
    const int wid_in = threadIdx.x >> 5;
    const int lane   = threadIdx.x & 31;
    const int gw = blockIdx.x * 8 + wid_in;
    const int b = gw >> 11;
    const int n = gw & (NN - 1);

    const float* pa = g_attn + ((size_t)b * NN + n) * NN;

    // pass 1: row max of approx
    float mx = -__int_as_float(0x7f800000);
    #pragma unroll
    for (int j = 0; j < 16; j++) {
        float4 v = ((const float4*)pa)[j * 32 + lane];
        mx = fmaxf(mx, fmaxf(fmaxf(v.x, v.y), fmaxf(v.z, v.w)));
    }
    #pragma unroll
    for (int off = 16; off >= 1; off >>= 1)
        mx = fmaxf(mx, __shfl_xor_sync(0xFFFFFFFFu, mx, off));

    // per-entry error bound (Cauchy-Schwarz) with margin
    float delta = 2.0f * 1.25f *
        (g_wln[n] * __uint_as_float(g_gnh[b]) + g_wn[n] * __uint_as_float(g_gnl[b]))
        + 1e-3f;
    float T = mx - delta;

    if (lane == 0) s_cnt[wid_in] = 0;
    __syncwarp();
    // pass 2: gather candidates
    #pragma unroll
    for (int j = 0; j < 64; j++) {
        int m = j * 32 + lane;
        if (pa[m] >= T) {
            int pos = atomicAdd(&s_cnt[wid_in], 1);
            if (pos < MAXCAND) s_cand[wid_in][pos] = m;
        }
    }
    __syncwarp();
    int cnt = s_cnt[wid_in];
    if (cnt > MAXCAND) cnt = MAXCAND;

    // exact recompute for each candidate: <Wq[n,:], G[:,m]> (G sym -> row m)
    const float* wrow = Wq + (size_t)n * NN;
    float best = -__int_as_float(0x7f800000);
    for (int k = 0; k < cnt; k++) {
        int m = s_cand[wid_in][k];
        const __nv_bfloat16* gh = g_Ghi + (size_t)b * NN2 + (size_t)m * NN;
        const __nv_bfloat16* gl = g_Glo + (size_t)b * NN2 + (size_t)m * NN;
        float s = 0.0f;
        #pragma unroll 8
        for (int i = lane; i < NN; i += 32)
            s += wrow[i] * (__bfloat162float(gh[i]) + __bfloat162float(gl[i]));
        #pragma unroll
        for (int off = 16; off >= 1; off >>= 1)
            s += __shfl_xor_sync(0xFFFFFFFFu, s, off);
        best = fmaxf(best, s);
    }
    if (lane == 0) g_m[b * NN + n] = best;
}

// out[b][n][c] = SCALE * rowmax[b][c] * v[b][n]
__global__ void out_kernel(float* __restrict__ out) {
    size_t idx = (size_t)blockIdx.x * 256 + threadIdx.x;
    int c = (int)(idx & (NN - 1));
    size_t r = idx >> 11;
    int n = (int)(r & (NN - 1));
    int b = (int)(r >> 11);
    out[idx] = SCALE * g_m[b * NN + c] * g_v[b * NN + n];
}

extern "C" void kernel_launch(void* const* d_in, const int* in_sizes, int n_in,
                              void* d_out, int out_size) {
    const float* x  = (const float*)d_in[0];
    const float* Wq = (const float*)d_in[1];
    float* out = (float*)d_out;

    cudaFuncSetAttribute(hgemm<0>, cudaFuncAttributeMaxDynamicSharedMemorySize, SMEM_BYTES);
    cudaFuncSetAttribute(hgemm<2>, cudaFuncAttributeMaxDynamicSharedMemorySize, SMEM_BYTES);

    init_kernel<<<(NB * NN + 255) / 256, 256>>>();
    mean_kernel<<<dim3(NB, NN / 256, NN / 256), 256>>>(x);
    convert_wq<<<NN, 256>>>(Wq);
    convert_x<<<(int)(((size_t)NB * NN2 / 4) / 256), 256>>>(x);

    __nv_bfloat16 *xh, *xl, *Gh, *Gl, *wh;
    float* attn;
    cudaGetSymbolAddress((void**)&xh, g_xhi);
    cudaGetSymbolAddress((void**)&xl, g_xlo);
    cudaGetSymbolAddress((void**)&Gh, g_Ghi);
    cudaGetSymbolAddress((void**)&Gl, g_Glo);
    cudaGetSymbolAddress((void**)&wh, g_wqhi);
    cudaGetSymbolAddress((void**)&attn, g_attn);

    // GEMM1: G = x x^T (bf16x3, upper-triangular tiles, mirrored store)
    hgemm<0><<<dim3(NUT, 1, NB), 256, SMEM_BYTES>>>(
        xh, xl, (size_t)NN2, xh, xl, (size_t)NN2, Gh, Gl, nullptr);

    // column norms of Gh/Gl (per-batch maxes) for the repair bound
    gnorm_kernel<<<dim3(NN, NB), 256>>>();

    // GEMM2 approx: attn ~= Wq_hi * G_hi (single pass), fp32 store
    hgemm<2><<<dim3(NMT, NMT, NB), 256, SMEM_BYTES>>>(
        wh, xl, 0, Gh, Gl, (size_t)NN2, nullptr, nullptr, attn);

    // candidate selection + exact repair -> g_m
    repair_kernel<<<NB * NN / 8, 256>>>(Wq);

    out_kernel<<<(int)(((size_t)NB * NN2) / 256), 256>>>(out);
}

// round 8
// speedup vs baseline: 6.7399x; 2.2666x over previous
#include <cuda_runtime.h>
#include <cuda_fp16.h>
#include <cstdint>

// B=8, N=C=2048, heads=8 -> scale = 1/16.
#define NB 8
#define NN 2048
#define NN2 (2048*2048)
#define SCALE 0.0625f

// ---------------- scratch ----------------------------------------------------
__device__ __align__(256) __half g_xh[(size_t)NB * NN2];   // x as fp16
__device__ __align__(256) __half g_G[(size_t)NB * NN2];    // G = x x^T as fp16 (full, symmetric)
__device__ __align__(256) __half g_wq[NN2];                // Wq as fp16
__device__ float        g_v[NB * NN];                      // column means of x
__device__ unsigned int g_m[NB * NN];                      // rowmax of attn (ordered uint)

__device__ __forceinline__ unsigned int float_ord(float f) {
    unsigned int u = __float_as_uint(f);
    return (u & 0x80000000u) ? ~u : (u | 0x80000000u);
}
__device__ __forceinline__ float ord_float(unsigned int o) {
    unsigned int u = (o & 0x80000000u) ? (o ^ 0x80000000u) : ~o;
    return __uint_as_float(u);
}

// ---- small kernels ----------------------------------------------------------
__global__ void init_kernel() {
    int i = blockIdx.x * 256 + threadIdx.x;
    if (i < NB * NN) { g_v[i] = 0.0f; g_m[i] = 0u; }
}

__global__ void mean_kernel(const float* __restrict__ x) {
    int b = blockIdx.x;
    int c = blockIdx.y * 256 + threadIdx.x;
    int n0 = blockIdx.z * 256;
    const float* xp = x + ((size_t)b * NN + n0) * NN + c;
    float s = 0.0f;
    #pragma unroll 8
    for (int n = 0; n < 256; n++) s += xp[(size_t)n * NN];
    atomicAdd(&g_v[b * NN + c], s * (1.0f / (float)NN));
}

__global__ void convert_wq(const float* __restrict__ Wq) {
    size_t g = (size_t)blockIdx.x * 256 + threadIdx.x;
    float4 f = ((const float4*)Wq)[g];
    ((__half2*)g_wq)[g * 2]     = __floats2half2_rn(f.x, f.y);
    ((__half2*)g_wq)[g * 2 + 1] = __floats2half2_rn(f.z, f.w);
}

__global__ void convert_x(const float* __restrict__ x) {
    size_t g = (size_t)blockIdx.x * 256 + threadIdx.x;
    float4 f = ((const float4*)x)[g];
    ((__half2*)g_xh)[g * 2]     = __floats2half2_rn(f.x, f.y);
    ((__half2*)g_xh)[g * 2 + 1] = __floats2half2_rn(f.z, f.w);
}

// ---------------- HMMA GEMM (mma.sync m16n8k16 fp16, single pass) ------------
#define BM 128
#define BN 128
#define BKT 32
#define PADK 40                         // fp16 per smem row; 80B stride
#define A_BYTES (BM * PADK * 2)         // 10240
#define STG_BYTES (2 * A_BYTES)
#define NSTG 4
#define SMEM_BYTES (NSTG * STG_BYTES)   // 81920 (> 128*130*2 = 33280 epi buffer)
#define NT 64                           // 64 k-tiles of 32 = K 2048
#define TFS 130                         // epi transpose buffer row stride (even)

#define NMT 16
#define NUT 136

__device__ __forceinline__ void ldsm4(uint32_t& d0, uint32_t& d1, uint32_t& d2,
                                      uint32_t& d3, uint32_t addr) {
    asm volatile("ldmatrix.sync.aligned.m8n8.x4.shared.b16 {%0,%1,%2,%3}, [%4];"
                 : "=r"(d0), "=r"(d1), "=r"(d2), "=r"(d3) : "r"(addr));
}
__device__ __forceinline__ void mma16816(float* c, const uint32_t* a, const uint32_t* b) {
    asm volatile(
        "mma.sync.aligned.m16n8k16.row.col.f32.f16.f16.f32 "
        "{%0,%1,%2,%3}, {%4,%5,%6,%7}, {%8,%9}, {%0,%1,%2,%3};"
        : "+f"(c[0]), "+f"(c[1]), "+f"(c[2]), "+f"(c[3])
        : "r"(a[0]), "r"(a[1]), "r"(a[2]), "r"(a[3]), "r"(b[0]), "r"(b[1]));
}
__device__ __forceinline__ void cp16(uint32_t dst, const void* src) {
    asm volatile("cp.async.cg.shared.global [%0], [%1], 16;" :: "r"(dst), "l"(src));
}

// MODE 0: symmetric GEMM (G = A A^T, upper tiles, direct + mirrored fp16 store)
// MODE 1: GEMM A*B^T with fused rowmax over N axis into g_m
template<int MODE>
__global__ __launch_bounds__(256, 2) void hgemm(
    const __half* __restrict__ A, size_t aStride,
    const __half* __restrict__ B, size_t bStride,
    __half* __restrict__ C)
{
    extern __shared__ __align__(16) char smem[];
    const int tid  = threadIdx.x;
    const int lane = tid & 31;
    const int w    = tid >> 5;
    const int wm   = w >> 1;
    const int wn   = w & 1;
    const int b    = blockIdx.z;

    int by, bx;
    if (MODE == 0) {                 // decode upper-tri linear index
        int t = blockIdx.x, i = 0;
        while (t >= NMT - i) { t -= NMT - i; i++; }
        by = i; bx = i + t;
    } else {
        by = blockIdx.y; bx = blockIdx.x;
    }
    const int rowA = by * BM;
    const int rowB = bx * BN;

    const __half* Ab = A + (size_t)b * aStride;
    const __half* Bb = B + (size_t)b * bStride;

    const uint32_t sbase = (uint32_t)__cvta_generic_to_shared(smem);

    const int q0 = tid * 2, q1 = tid * 2 + 1;
    const int r0c = q0 >> 2, k0c = q0 & 3;
    const int r1c = q1 >> 2, k1c = q1 & 3;

    auto load_stage = [&](int tile) {
        uint32_t sb = sbase + (tile & (NSTG - 1)) * STG_BYTES;
        const int kk = tile * BKT;
        cp16(sb + r0c * 80 + k0c * 16, Ab + (size_t)(rowA + r0c) * NN + kk + k0c * 8);
        cp16(sb + r1c * 80 + k1c * 16, Ab + (size_t)(rowA + r1c) * NN + kk + k1c * 8);
        cp16(sb + A_BYTES + r0c * 80 + k0c * 16, Bb + (size_t)(rowB + r0c) * NN + kk + k0c * 8);
        cp16(sb + A_BYTES + r1c * 80 + k1c * 16, Bb + (size_t)(rowB + r1c) * NN + kk + k1c * 8);
    };

    const int rowoff = (lane & 7) + ((lane >> 3) & 1) * 8;
    const int koff   = (lane >> 4) * 8;

    float acc[2][8][4];
    #pragma unroll
    for (int i = 0; i < 2; i++)
        #pragma unroll
        for (int j = 0; j < 8; j++)
            #pragma unroll
            for (int k = 0; k < 4; k++) acc[i][j][k] = 0.0f;

    load_stage(0); asm volatile("cp.async.commit_group;");
    load_stage(1); asm volatile("cp.async.commit_group;");
    load_stage(2); asm volatile("cp.async.commit_group;");

    for (int t = 0; t < NT; t++) {
        asm volatile("cp.async.wait_group 2;");
        __syncthreads();
        if (t + 3 < NT) load_stage(t + 3);
        asm volatile("cp.async.commit_group;");

        uint32_t sA = sbase + (t & (NSTG - 1)) * STG_BYTES;
        uint32_t sB = sA + A_BYTES;
        #pragma unroll
        for (int ks = 0; ks < 2; ks++) {
            const int kbase = ks * 16 + koff;
            uint32_t a[2][4];
            #pragma unroll
            for (int mt = 0; mt < 2; mt++) {
                uint32_t off = ((wm * 32 + mt * 16 + rowoff) * PADK + kbase) * 2;
                ldsm4(a[mt][0], a[mt][1], a[mt][2], a[mt][3], sA + off);
            }
            uint32_t bb[8][2];
            #pragma unroll
            for (int nt2 = 0; nt2 < 4; nt2++) {
                uint32_t off = ((wn * 64 + nt2 * 16 + rowoff) * PADK + kbase) * 2;
                uint32_t d0, d1, d2, d3;
                ldsm4(d0, d1, d2, d3, sB + off);
                bb[nt2 * 2][0] = d0;     bb[nt2 * 2][1] = d2;
                bb[nt2 * 2 + 1][0] = d1; bb[nt2 * 2 + 1][1] = d3;
            }
            #pragma unroll
            for (int mt = 0; mt < 2; mt++)
                #pragma unroll
                for (int nt = 0; nt < 8; nt++)
                    mma16816(acc[mt][nt], a[mt], bb[nt]);
        }
    }
    asm volatile("cp.async.wait_group 0;");

    if (MODE == 0) {
        __half* cg = C + (size_t)b * NN2;
        // direct fp16 store of tile (by,bx)
        #pragma unroll
        for (int mt = 0; mt < 2; mt++) {
            int r = rowA + wm * 32 + mt * 16 + (lane >> 2);
            #pragma unroll
            for (int nt = 0; nt < 8; nt++) {
                int c = rowB + wn * 64 + nt * 8 + (lane & 3) * 2;
                *(__half2*)(cg + (size_t)r * NN + c) =
                    __floats2half2_rn(acc[mt][nt][0], acc[mt][nt][1]);
                *(__half2*)(cg + (size_t)(r + 8) * NN + c) =
                    __floats2half2_rn(acc[mt][nt][2], acc[mt][nt][3]);
            }
        }
        if (by != bx) {
            // stage fp16 tile in smem (row stride TFS halfs, even -> half2 aligned),
            // then write mirrored tile (bx,by)
            __half* tf = (__half*)smem;
            __syncthreads();   // pipeline smem reuse
            #pragma unroll
            for (int mt = 0; mt < 2; mt++) {
                int rl = wm * 32 + mt * 16 + (lane >> 2);
                #pragma unroll
                for (int nt = 0; nt < 8; nt++) {
                    int clc = wn * 64 + nt * 8 + (lane & 3) * 2;
                    *(__half2*)&tf[rl * TFS + clc] =
                        __floats2half2_rn(acc[mt][nt][0], acc[mt][nt][1]);
                    *(__half2*)&tf[(rl + 8) * TFS + clc] =
                        __floats2half2_rn(acc[mt][nt][2], acc[mt][nt][3]);
                }
            }
            __syncthreads();
            const int cc = tid >> 1;            // original col -> mirrored row
            const int hh = (tid & 1) * 64;
            __half* cp = cg + (size_t)(rowB + cc) * NN + rowA + hh;
            #pragma unroll
            for (int g = 0; g < 8; g++) {
                __align__(16) __half hb[8];
                #pragma unroll
                for (int e = 0; e < 8; e++)
                    hb[e] = tf[(hh + g * 8 + e) * TFS + cc];
                *(uint4*)(cp + g * 8) = *(uint4*)hb;
            }
        }
    } else {
        // fused rowmax over the N axis
        #pragma unroll
        for (int mt = 0; mt < 2; mt++) {
            float m0 = -__int_as_float(0x7f800000), m1 = m0;
            #pragma unroll
            for (int nt = 0; nt < 8; nt++) {
                m0 = fmaxf(m0, fmaxf(acc[mt][nt][0], acc[mt][nt][1]));
                m1 = fmaxf(m1, fmaxf(acc[mt][nt][2], acc[mt][nt][3]));
            }
            m0 = fmaxf(m0, __shfl_xor_sync(0xFFFFFFFFu, m0, 1));
            m0 = fmaxf(m0, __shfl_xor_sync(0xFFFFFFFFu, m0, 2));
            m1 = fmaxf(m1, __shfl_xor_sync(0xFFFFFFFFu, m1, 1));
            m1 = fmaxf(m1, __shfl_xor_sync(0xFFFFFFFFu, m1, 2));
            if ((lane & 3) == 0) {
                int r = rowA + wm * 32 + mt * 16 + (lane >> 2);
                atomicMax(&g_m[b * NN + r], float_ord(m0));
                atomicMax(&g_m[b * NN + r + 8], float_ord(m1));
            }
        }
    }
}

// out[b][n][c] = SCALE * rowmax[b][c] * v[b][n]
__global__ void out_kernel(float* __restrict__ out) {
    size_t idx = (size_t)blockIdx.x * 256 + threadIdx.x;
    int c = (int)(idx & (NN - 1));
    size_t r = idx >> 11;
    int n = (int)(r & (NN - 1));
    int b = (int)(r >> 11);
    out[idx] = SCALE * ord_float(g_m[b * NN + c]) * g_v[b * NN + n];
}

extern "C" void kernel_launch(void* const* d_in, const int* in_sizes, int n_in,
                              void* d_out, int out_size) {
    const float* x  = (const float*)d_in[0];
    const float* Wq = (const float*)d_in[1];
    float* out = (float*)d_out;

    cudaFuncSetAttribute(hgemm<0>, cudaFuncAttributeMaxDynamicSharedMemorySize, SMEM_BYTES);
    cudaFuncSetAttribute(hgemm<1>, cudaFuncAttributeMaxDynamicSharedMemorySize, SMEM_BYTES);

    init_kernel<<<(NB * NN + 255) / 256, 256>>>();
    mean_kernel<<<dim3(NB, NN / 256, NN / 256), 256>>>(x);
    convert_wq<<<NN2 / 4 / 256, 256>>>(Wq);
    convert_x<<<(int)(((size_t)NB * NN2 / 4) / 256), 256>>>(x);

    __half *xh, *G, *wq;
    cudaGetSymbolAddress((void**)&xh, g_xh);
    cudaGetSymbolAddress((void**)&G,  g_G);
    cudaGetSymbolAddress((void**)&wq, g_wq);

    // GEMM1: G = x x^T (fp16 single pass, upper-tri tiles, mirrored store)
    hgemm<0><<<dim3(NUT, 1, NB), 256, SMEM_BYTES>>>(
        xh, (size_t)NN2, xh, (size_t)NN2, G);

    // GEMM2: attn = Wq * G^T (G symmetric -> rows), fused rowmax
    hgemm<1><<<dim3(NMT, NMT, NB), 256, SMEM_BYTES>>>(
        wq, 0, G, (size_t)NN2, nullptr);

    out_kernel<<<(int)(((size_t)NB * NN2) / 256), 256>>>(out);
}